// round 4
// baseline (speedup 1.0000x reference)
#include <cuda_runtime.h>
#include <math.h>

#define NH 8
#define DHD 64
#define DMOD 512
#define SEQ 1024
#define NB 2
#define NBS (NB*SEQ)

// scratch (static device arrays: no allocation allowed)
__device__ float g_q[NB*NH*SEQ*DHD];
__device__ float g_k[NB*NH*SEQ*DHD];
__device__ float g_v[NB*NH*SEQ*DHD];
__device__ float g_attn[NBS*DMOD];
__device__ float g_y[NBS*DMOD];
__device__ float g_table[65*DHD];

// ---------------------------------------------------------------------------
// sincos relative-position table: pe[pos, 2j] = sin(pos*div_j), pe[pos,2j+1]=cos
__global__ void build_table_kernel() {
    int i = blockIdx.x * blockDim.x + threadIdx.x;
    if (i < 65*32) {
        int pos = i >> 5, j = i & 31;
        float div = expf((float)(2*j) * (-9.210340371976184f / 64.0f));
        float a = (float)pos * div;
        g_table[pos*64 + 2*j]     = sinf(a);
        g_table[pos*64 + 2*j + 1] = cosf(a);
    }
}

// ---------------------------------------------------------------------------
// C = A @ W^T + bias. A:[2048,512], W:[512,512] row-major.
// outsel 0/1/2: write g_q/g_k/g_v in [b,h,s,d] layout.
// outsel 3: A = g_attn (Asel=1), add residual, write g_y plain [n][m].
__global__ __launch_bounds__(256) void gemm512_kernel(
    const float* __restrict__ Ain, const float* __restrict__ W,
    const float* __restrict__ bias, const float* __restrict__ res,
    int Asel, int outsel)
{
    __shared__ float As[64][20];   // [n][k] padded
    __shared__ float Ws[16][68];   // [k][m] padded
    const float* A = Asel ? g_attn : Ain;
    int tid = threadIdx.x;
    int tx = tid & 15, ty = tid >> 4;
    int n0 = blockIdx.y * 64;
    int m0 = blockIdx.x * 64;
    float acc[4][4] = {};
    int lrow = tid >> 2, lc4 = (tid & 3) * 4;
    for (int k0 = 0; k0 < DMOD; k0 += 16) {
        float4 a4 = *(const float4*)(A + (size_t)(n0 + lrow)*DMOD + k0 + lc4);
        *(float4*)&As[lrow][lc4] = a4;
        float4 w4 = *(const float4*)(W + (size_t)(m0 + lrow)*DMOD + k0 + lc4);
        Ws[lc4+0][lrow] = w4.x; Ws[lc4+1][lrow] = w4.y;
        Ws[lc4+2][lrow] = w4.z; Ws[lc4+3][lrow] = w4.w;
        __syncthreads();
#pragma unroll
        for (int kk = 0; kk < 16; kk++) {
            float4 wf = *(const float4*)&Ws[kk][tx*4];
            float af[4];
#pragma unroll
            for (int r = 0; r < 4; r++) af[r] = As[ty*4+r][kk];
#pragma unroll
            for (int r = 0; r < 4; r++) {
                acc[r][0] += af[r]*wf.x; acc[r][1] += af[r]*wf.y;
                acc[r][2] += af[r]*wf.z; acc[r][3] += af[r]*wf.w;
            }
        }
        __syncthreads();
    }
#pragma unroll
    for (int r = 0; r < 4; r++) {
        int n = n0 + ty*4 + r;
#pragma unroll
        for (int c = 0; c < 4; c++) {
            int m = m0 + tx*4 + c;
            float v = acc[r][c] + bias[m];
            if (outsel < 3) {
                int b = n >> 10, s = n & 1023, h = m >> 6, d = m & 63;
                float* dst = (outsel == 0) ? g_q : ((outsel == 1) ? g_k : g_v);
                dst[(((size_t)(b*NH + h) << 10) + s)*DHD + d] = v;
            } else {
                v += res[(size_t)n*DMOD + m];
                g_y[(size_t)n*DMOD + m] = v;
            }
        }
    }
}

// ---------------------------------------------------------------------------
// Fused causal flash attention with relative-position bias (scores & values).
// One block per (q-tile of 64, b*h). 256 threads. BK = 32.
// Static shared only (44.5 KB) — no cudaFuncSetAttribute needed.
__global__ __launch_bounds__(256) void attn_kernel() {
    __shared__ float Qs[64][68];    // [q][d]
    __shared__ float KP[64][36];    // phase A: K^T as [d][k] (k<32); phase B: P [q][k]
    __shared__ float Vs[32][68];    // [k][d]
    __shared__ float rel[64][34];   // [q][j], j=0..32
    __shared__ float mrow[64], lrowv[64];

    int tid = threadIdx.x;
    int tx = tid & 15, ty = tid >> 4;
    int qb = blockIdx.x;   // q-tile 0..15 (64 rows)
    int bh = blockIdx.y;   // 0..15
    const float* qptr = g_q + ((size_t)bh*SEQ + qb*64)*DHD;

#pragma unroll
    for (int i = 0; i < 4; i++) {
        int idx = tid + 256*i;
        int row = idx >> 4, c4 = (idx & 15) * 4;
        *(float4*)&Qs[row][c4] = *(const float4*)(qptr + row*DHD + c4);
    }
    __syncthreads();
    // rel[row][j] = q_row . table[j], j in [0,32]
    for (int pidx = tid; pidx < 64*33; pidx += 256) {
        int row = pidx / 33;
        int j = pidx - row*33;
        const float* t = g_table + j*DHD;
        float s = 0.f;
#pragma unroll
        for (int d = 0; d < 64; d += 4) {
            float4 tv = *(const float4*)(t + d);
            s += Qs[row][d]*tv.x + Qs[row][d+1]*tv.y
               + Qs[row][d+2]*tv.z + Qs[row][d+3]*tv.w;
        }
        rel[row][j] = s;
    }

    float m_i[4], l_i[4], o[4][4];
#pragma unroll
    for (int r = 0; r < 4; r++) {
        m_i[r] = -1e30f; l_i[r] = 0.f;
#pragma unroll
        for (int c = 0; c < 4; c++) o[r][c] = 0.f;
    }

    int ntile = 2*qb + 2;     // 32-wide key tiles covering kg <= qb*64+63
    for (int kb = 0; kb < ntile; kb++) {
        __syncthreads();      // KP/Vs free for reload (covers rel writes on iter 0)
        const float* kptr = g_k + ((size_t)bh*SEQ + kb*32)*DHD;
        const float* vptr = g_v + ((size_t)bh*SEQ + kb*32)*DHD;
#pragma unroll
        for (int i = 0; i < 2; i++) {
            int idx = tid + 256*i;            // 512 = 32 rows * 16 float4
            int row = idx >> 4, c4 = (idx & 15) * 4;
            float4 kv = *(const float4*)(kptr + row*DHD + c4);
            KP[c4+0][row] = kv.x; KP[c4+1][row] = kv.y;
            KP[c4+2][row] = kv.z; KP[c4+3][row] = kv.w;
            *(float4*)&Vs[row][c4] = *(const float4*)(vptr + row*DHD + c4);
        }
        __syncthreads();

        // S = Q @ K^T  (64 x 32 tile; each thread: 4 rows x 2 cols)
        float s0[4] = {}, s1[4] = {};
#pragma unroll
        for (int kk = 0; kk < 64; kk++) {
            float2 kf = *(const float2*)&KP[kk][tx*2];
#pragma unroll
            for (int rr = 0; rr < 4; rr++) {
                float qv = Qs[ty*4+rr][kk];
                s0[rr] += qv*kf.x; s1[rr] += qv*kf.y;
            }
        }

        float p0[4], p1[4];
#pragma unroll
        for (int rr = 0; rr < 4; rr++) {
            int qg = qb*64 + ty*4 + rr;
            int kg0 = kb*32 + tx*2;
            float v0, v1;
            if (kg0 > qg) v0 = -1e30f;
            else { int j = kg0 - qg + 32; if (j < 0) j = 0;
                   v0 = (s0[rr] + rel[ty*4+rr][j]) * 0.125f; }
            if (kg0 + 1 > qg) v1 = -1e30f;
            else { int j = kg0 + 1 - qg + 32; if (j < 0) j = 0;
                   v1 = (s1[rr] + rel[ty*4+rr][j]) * 0.125f; }
            float mt = fmaxf(v0, v1);
#pragma unroll
            for (int off = 8; off >= 1; off >>= 1)
                mt = fmaxf(mt, __shfl_xor_sync(0xffffffffu, mt, off));
            float mn = fmaxf(m_i[rr], mt);
            float sc = __expf(m_i[rr] - mn);
            p0[rr] = __expf(v0 - mn);
            p1[rr] = __expf(v1 - mn);
            float rs = p0[rr] + p1[rr];
#pragma unroll
            for (int off = 8; off >= 1; off >>= 1)
                rs += __shfl_xor_sync(0xffffffffu, rs, off);
            l_i[rr] = l_i[rr]*sc + rs;
            m_i[rr] = mn;
#pragma unroll
            for (int c = 0; c < 4; c++) o[rr][c] *= sc;
        }
        __syncthreads();      // all K reads done before P overwrites KP
#pragma unroll
        for (int rr = 0; rr < 4; rr++)
            *(float2*)&KP[ty*4+rr][tx*2] = make_float2(p0[rr], p1[rr]);
        __syncthreads();

        // O += P @ V  (64 x 64; each thread: 4 rows x 4 cols over d)
#pragma unroll
        for (int kk = 0; kk < 32; kk++) {
            float4 vf = *(const float4*)&Vs[kk][tx*4];
#pragma unroll
            for (int rr = 0; rr < 4; rr++) {
                float pv = KP[ty*4+rr][kk];
                o[rr][0] += pv*vf.x; o[rr][1] += pv*vf.y;
                o[rr][2] += pv*vf.z; o[rr][3] += pv*vf.w;
            }
        }
    }

    // finalize p@v part
#pragma unroll
    for (int rr = 0; rr < 4; rr++) {
        float inv = 1.0f / l_i[rr];
#pragma unroll
        for (int c = 0; c < 4; c++) o[rr][c] *= inv;
    }
    if (tx == 0) {
#pragma unroll
        for (int rr = 0; rr < 4; rr++) { mrow[ty*4+rr] = m_i[rr]; lrowv[ty*4+rr] = l_i[rr]; }
    }
    __syncthreads();

    // rel-V band: p(q, q-mm), mm = 0..31 (recompute; bucket identity:
    // out2 = table[0] + sum_mm p * (table[32-mm] - table[0]) since sum_k p = 1)
    float (*bandp)[32] = (float(*)[32])&KP[0][0];   // reuse (P dead)
#pragma unroll
    for (int i = 0; i < 8; i++) {
        int pidx = tid + 256*i;          // 2048 = 64 rows * 32 band offsets
        int row = pidx >> 5, mm = pidx & 31;
        int qg = qb*64 + row;
        int kg = qg - mm;
        float p = 0.f;
        if (kg >= 0) {
            const float* kvec = g_k + ((size_t)bh*SEQ + kg)*DHD;
            float dot = 0.f;
#pragma unroll
            for (int d = 0; d < 64; d += 4) {
                float4 kv = *(const float4*)(kvec + d);
                dot += Qs[row][d]*kv.x + Qs[row][d+1]*kv.y
                     + Qs[row][d+2]*kv.z + Qs[row][d+3]*kv.w;
            }
            float s = (dot + rel[row][32 - mm]) * 0.125f;
            p = __expf(s - mrow[row]) / lrowv[row];
        }
        bandp[row][mm] = p;
    }
    __syncthreads();

    float4 t0v = *(const float4*)&g_table[tx*4];
    float4 a2[4];
#pragma unroll
    for (int rr = 0; rr < 4; rr++) a2[rr] = t0v;
    for (int mm = 0; mm < 32; mm++) {
        float4 tv = *(const float4*)&g_table[(32 - mm)*64 + tx*4];
        float4 dv = make_float4(tv.x - t0v.x, tv.y - t0v.y, tv.z - t0v.z, tv.w - t0v.w);
#pragma unroll
        for (int rr = 0; rr < 4; rr++) {
            float pm = bandp[ty*4+rr][mm];
            a2[rr].x += pm*dv.x; a2[rr].y += pm*dv.y;
            a2[rr].z += pm*dv.z; a2[rr].w += pm*dv.w;
        }
    }
    int b = bh >> 3, h = bh & 7;
#pragma unroll
    for (int rr = 0; rr < 4; rr++) {
        int sg = qb*64 + ty*4 + rr;
        float4 ov = make_float4(o[rr][0] + a2[rr].x, o[rr][1] + a2[rr].y,
                                o[rr][2] + a2[rr].z, o[rr][3] + a2[rr].w);
        *(float4*)&g_attn[((size_t)b*SEQ + sg)*DMOD + h*64 + tx*4] = ov;
    }
}

// ---------------------------------------------------------------------------
// LayerNorm variant: unbiased std (ddof=1), divide by (std + eps)
__global__ __launch_bounds__(128) void ln_kernel(const float* __restrict__ lnw,
                                                 const float* __restrict__ lnb,
                                                 float* __restrict__ out)
{
    int rowid = blockIdx.x;
    const float* x = g_y + (size_t)rowid * DMOD;
    int tid = threadIdx.x;
    float4 xv = *(const float4*)(x + tid*4);
    float s  = xv.x + xv.y + xv.z + xv.w;
    float ss = xv.x*xv.x + xv.y*xv.y + xv.z*xv.z + xv.w*xv.w;
#pragma unroll
    for (int off = 16; off >= 1; off >>= 1) {
        s  += __shfl_xor_sync(0xffffffffu, s, off);
        ss += __shfl_xor_sync(0xffffffffu, ss, off);
    }
    __shared__ float rs[4], rss[4];
    int warp = tid >> 5;
    if ((tid & 31) == 0) { rs[warp] = s; rss[warp] = ss; }
    __syncthreads();
    float tS  = rs[0] + rs[1] + rs[2] + rs[3];
    float tSS = rss[0] + rss[1] + rss[2] + rss[3];
    float mean = tS * (1.0f/512.0f);
    float var = (tSS - 512.0f*mean*mean) * (1.0f/511.0f);
    var = fmaxf(var, 0.f);
    float inv = 1.0f / (sqrtf(var) + 1e-6f);
    float4 wv = *(const float4*)(lnw + tid*4);
    float4 bv = *(const float4*)(lnb + tid*4);
    float4 ov;
    ov.x = wv.x * (xv.x - mean) * inv + bv.x;
    ov.y = wv.y * (xv.y - mean) * inv + bv.y;
    ov.z = wv.z * (xv.z - mean) * inv + bv.z;
    ov.w = wv.w * (xv.w - mean) * inv + bv.w;
    *(float4*)(out + (size_t)rowid*DMOD + tid*4) = ov;
}

// ---------------------------------------------------------------------------
extern "C" void kernel_launch(void* const* d_in, const int* in_sizes, int n_in,
                              void* d_out, int out_size)
{
    const float* query = (const float*)d_in[0];
    const float* key_  = (const float*)d_in[1];
    const float* value = (const float*)d_in[2];
    const float* Wq = (const float*)d_in[3];
    const float* bq = (const float*)d_in[4];
    const float* Wk = (const float*)d_in[5];
    const float* bk = (const float*)d_in[6];
    const float* Wv = (const float*)d_in[7];
    const float* bv = (const float*)d_in[8];
    const float* Wo = (const float*)d_in[9];
    const float* bo = (const float*)d_in[10];
    const float* lnw = (const float*)d_in[11];
    const float* lnb = (const float*)d_in[12];
    float* out = (float*)d_out;
    (void)in_sizes; (void)n_in; (void)out_size;

    build_table_kernel<<<3, 1024>>>();
    dim3 ggrid(8, 32);  // (m tiles, n tiles)
    gemm512_kernel<<<ggrid, 256>>>(query, Wq, bq, nullptr, 0, 0);
    gemm512_kernel<<<ggrid, 256>>>(key_,  Wk, bk, nullptr, 0, 1);
    gemm512_kernel<<<ggrid, 256>>>(value, Wv, bv, nullptr, 0, 2);
    attn_kernel<<<dim3(16, 16), 256>>>();
    gemm512_kernel<<<ggrid, 256>>>(nullptr, Wo, bo, query, 1, 3);
    ln_kernel<<<NBS, 128>>>(lnw, lnb, out);
}

// round 6
// speedup vs baseline: 1.1493x; 1.1493x over previous
#include <cuda_runtime.h>
#include <math.h>

#define NH 8
#define DHD 64
#define DMOD 512
#define SEQ 1024
#define NB 2
#define NBS (NB*SEQ)

// scratch (static device arrays: no allocation allowed)
__device__ float g_q[NB*NH*SEQ*DHD];
__device__ float g_k[NB*NH*SEQ*DHD];
__device__ float g_v[NB*NH*SEQ*DHD];
__device__ float g_attn[NBS*DMOD];
__device__ float g_y[NBS*DMOD];
__device__ float g_table[65*DHD];

// ---------------------------------------------------------------------------
// sincos relative-position table: pe[pos, 2j] = sin(pos*div_j), pe[pos,2j+1]=cos
__global__ void build_table_kernel() {
    int i = blockIdx.x * blockDim.x + threadIdx.x;
    if (i < 65*32) {
        int pos = i >> 5, j = i & 31;
        float div = expf((float)(2*j) * (-9.210340371976184f / 64.0f));
        float a = (float)pos * div;
        g_table[pos*64 + 2*j]     = sinf(a);
        g_table[pos*64 + 2*j + 1] = cosf(a);
    }
}

// ---------------------------------------------------------------------------
// Merged Q/K/V projection: z selects (A, W, bias, dst). C = A @ W^T + bias,
// scattered to [b,h,s,d]. 64x64 tile, k-step 32, 4x4 microtile.
__global__ __launch_bounds__(256) void gemm_qkv_kernel(
    const float* __restrict__ Aq, const float* __restrict__ Ak_, const float* __restrict__ Av,
    const float* __restrict__ Wq, const float* __restrict__ Wk, const float* __restrict__ Wv,
    const float* __restrict__ bq, const float* __restrict__ bk, const float* __restrict__ bv)
{
    __shared__ float As[64][36];   // [n][k]
    __shared__ float Ws[32][68];   // [k][m]
    int z = blockIdx.z;
    const float* A    = (z == 0) ? Aq : ((z == 1) ? Ak_ : Av);
    const float* W    = (z == 0) ? Wq : ((z == 1) ? Wk : Wv);
    const float* bias = (z == 0) ? bq : ((z == 1) ? bk : bv);
    float* dst        = (z == 0) ? g_q : ((z == 1) ? g_k : g_v);

    int tid = threadIdx.x;
    int tx = tid & 15, ty = tid >> 4;
    int n0 = blockIdx.y * 64;
    int m0 = blockIdx.x * 64;
    float acc[4][4] = {};
    for (int k0 = 0; k0 < DMOD; k0 += 32) {
#pragma unroll
        for (int j = 0; j < 2; j++) {
            int id = tid + 256*j;
            int row = id >> 3, c4 = (id & 7) * 4;
            *(float4*)&As[row][c4] = *(const float4*)(A + (size_t)(n0 + row)*DMOD + k0 + c4);
        }
#pragma unroll
        for (int j = 0; j < 2; j++) {
            int id = tid + 256*j;
            int row = id >> 3, c4 = (id & 7) * 4;
            float4 w4 = *(const float4*)(W + (size_t)(m0 + row)*DMOD + k0 + c4);
            Ws[c4+0][row] = w4.x; Ws[c4+1][row] = w4.y;
            Ws[c4+2][row] = w4.z; Ws[c4+3][row] = w4.w;
        }
        __syncthreads();
#pragma unroll
        for (int kk = 0; kk < 32; kk++) {
            float4 wf = *(const float4*)&Ws[kk][tx*4];
            float af[4];
#pragma unroll
            for (int r = 0; r < 4; r++) af[r] = As[ty*4+r][kk];
#pragma unroll
            for (int r = 0; r < 4; r++) {
                acc[r][0] += af[r]*wf.x; acc[r][1] += af[r]*wf.y;
                acc[r][2] += af[r]*wf.z; acc[r][3] += af[r]*wf.w;
            }
        }
        __syncthreads();
    }
#pragma unroll
    for (int r = 0; r < 4; r++) {
        int n = n0 + ty*4 + r;
        int b = n >> 10, s = n & 1023;
#pragma unroll
        for (int c = 0; c < 4; c++) {
            int m = m0 + tx*4 + c;
            int h = m >> 6, d = m & 63;
            dst[(((size_t)(b*NH + h) << 10) + s)*DHD + d] = acc[r][c] + bias[m];
        }
    }
}

// ---------------------------------------------------------------------------
// Output projection: y = attn @ Wo^T + bo + residual, plain [n][m] layout.
__global__ __launch_bounds__(256) void gemm_out_kernel(
    const float* __restrict__ W, const float* __restrict__ bias,
    const float* __restrict__ res)
{
    __shared__ float As[64][36];
    __shared__ float Ws[32][68];
    const float* A = g_attn;
    int tid = threadIdx.x;
    int tx = tid & 15, ty = tid >> 4;
    int n0 = blockIdx.y * 64;
    int m0 = blockIdx.x * 64;
    float acc[4][4] = {};
    for (int k0 = 0; k0 < DMOD; k0 += 32) {
#pragma unroll
        for (int j = 0; j < 2; j++) {
            int id = tid + 256*j;
            int row = id >> 3, c4 = (id & 7) * 4;
            *(float4*)&As[row][c4] = *(const float4*)(A + (size_t)(n0 + row)*DMOD + k0 + c4);
        }
#pragma unroll
        for (int j = 0; j < 2; j++) {
            int id = tid + 256*j;
            int row = id >> 3, c4 = (id & 7) * 4;
            float4 w4 = *(const float4*)(W + (size_t)(m0 + row)*DMOD + k0 + c4);
            Ws[c4+0][row] = w4.x; Ws[c4+1][row] = w4.y;
            Ws[c4+2][row] = w4.z; Ws[c4+3][row] = w4.w;
        }
        __syncthreads();
#pragma unroll
        for (int kk = 0; kk < 32; kk++) {
            float4 wf = *(const float4*)&Ws[kk][tx*4];
            float af[4];
#pragma unroll
            for (int r = 0; r < 4; r++) af[r] = As[ty*4+r][kk];
#pragma unroll
            for (int r = 0; r < 4; r++) {
                acc[r][0] += af[r]*wf.x; acc[r][1] += af[r]*wf.y;
                acc[r][2] += af[r]*wf.z; acc[r][3] += af[r]*wf.w;
            }
        }
        __syncthreads();
    }
#pragma unroll
    for (int r = 0; r < 4; r++) {
        int n = n0 + ty*4 + r;
#pragma unroll
        for (int c = 0; c < 4; c++) {
            int m = m0 + tx*4 + c;
            g_y[(size_t)n*DMOD + m] = acc[r][c] + bias[m] + res[(size_t)n*DMOD + m];
        }
    }
}

// ---------------------------------------------------------------------------
// Fused causal flash attention with relative-position bias (scores & values).
// 1-D grid of 256 blocks, heavy q-tiles launched FIRST (qb = 15 - bid/16).
// 256 threads. BK = 32. Static shared only (44.5 KB).
__global__ __launch_bounds__(256) void attn_kernel() {
    __shared__ float Qs[64][68];    // [q][d]
    __shared__ float KP[64][36];    // phase A: K^T as [d][k] (k<32); phase B: P [q][k]
    __shared__ float Vs[32][68];    // [k][d]
    __shared__ float rel[64][34];   // [q][j], j=0..32
    __shared__ float mrow[64], lrowv[64];

    int tid = threadIdx.x;
    int tx = tid & 15, ty = tid >> 4;
    int bid = blockIdx.x;
    int qb = 15 - (bid >> 4);   // heavy tiles first
    int bh = bid & 15;
    const float* qptr = g_q + ((size_t)bh*SEQ + qb*64)*DHD;

#pragma unroll
    for (int i = 0; i < 4; i++) {
        int idx = tid + 256*i;
        int row = idx >> 4, c4 = (idx & 15) * 4;
        *(float4*)&Qs[row][c4] = *(const float4*)(qptr + row*DHD + c4);
    }
    __syncthreads();
    // rel[row][j] = q_row . table[j], j in [0,32]
    for (int pidx = tid; pidx < 64*33; pidx += 256) {
        int row = pidx / 33;
        int j = pidx - row*33;
        const float* t = g_table + j*DHD;
        float s = 0.f;
#pragma unroll
        for (int d = 0; d < 64; d += 4) {
            float4 tv = *(const float4*)(t + d);
            s += Qs[row][d]*tv.x + Qs[row][d+1]*tv.y
               + Qs[row][d+2]*tv.z + Qs[row][d+3]*tv.w;
        }
        rel[row][j] = s;
    }

    float m_i[4], l_i[4], o[4][4];
#pragma unroll
    for (int r = 0; r < 4; r++) {
        m_i[r] = -1e30f; l_i[r] = 0.f;
#pragma unroll
        for (int c = 0; c < 4; c++) o[r][c] = 0.f;
    }

    int ntile = 2*qb + 2;     // 32-wide key tiles covering kg <= qb*64+63
    for (int kb = 0; kb < ntile; kb++) {
        __syncthreads();      // KP/Vs free for reload (covers rel writes on iter 0)
        const float* kptr = g_k + ((size_t)bh*SEQ + kb*32)*DHD;
        const float* vptr = g_v + ((size_t)bh*SEQ + kb*32)*DHD;
#pragma unroll
        for (int i = 0; i < 2; i++) {
            int idx = tid + 256*i;            // 512 = 32 rows * 16 float4
            int row = idx >> 4, c4 = (idx & 15) * 4;
            float4 kv = *(const float4*)(kptr + row*DHD + c4);
            KP[c4+0][row] = kv.x; KP[c4+1][row] = kv.y;
            KP[c4+2][row] = kv.z; KP[c4+3][row] = kv.w;
            *(float4*)&Vs[row][c4] = *(const float4*)(vptr + row*DHD + c4);
        }
        __syncthreads();

        // S = Q @ K^T  (64 x 32 tile; each thread: 4 rows x 2 cols)
        float s0[4] = {}, s1[4] = {};
#pragma unroll
        for (int kk = 0; kk < 64; kk++) {
            float2 kf = *(const float2*)&KP[kk][tx*2];
#pragma unroll
            for (int rr = 0; rr < 4; rr++) {
                float qv = Qs[ty*4+rr][kk];
                s0[rr] += qv*kf.x; s1[rr] += qv*kf.y;
            }
        }

        float p0[4], p1[4];
#pragma unroll
        for (int rr = 0; rr < 4; rr++) {
            int qg = qb*64 + ty*4 + rr;
            int kg0 = kb*32 + tx*2;
            float v0, v1;
            if (kg0 > qg) v0 = -1e30f;
            else { int j = kg0 - qg + 32; if (j < 0) j = 0;
                   v0 = (s0[rr] + rel[ty*4+rr][j]) * 0.125f; }
            if (kg0 + 1 > qg) v1 = -1e30f;
            else { int j = kg0 + 1 - qg + 32; if (j < 0) j = 0;
                   v1 = (s1[rr] + rel[ty*4+rr][j]) * 0.125f; }
            float mt = fmaxf(v0, v1);
#pragma unroll
            for (int off = 8; off >= 1; off >>= 1)
                mt = fmaxf(mt, __shfl_xor_sync(0xffffffffu, mt, off));
            float mn = fmaxf(m_i[rr], mt);
            float sc = __expf(m_i[rr] - mn);
            p0[rr] = __expf(v0 - mn);
            p1[rr] = __expf(v1 - mn);
            float rs = p0[rr] + p1[rr];
#pragma unroll
            for (int off = 8; off >= 1; off >>= 1)
                rs += __shfl_xor_sync(0xffffffffu, rs, off);
            l_i[rr] = l_i[rr]*sc + rs;
            m_i[rr] = mn;
#pragma unroll
            for (int c = 0; c < 4; c++) o[rr][c] *= sc;
        }
        __syncthreads();      // all K reads done before P overwrites KP
#pragma unroll
        for (int rr = 0; rr < 4; rr++)
            *(float2*)&KP[ty*4+rr][tx*2] = make_float2(p0[rr], p1[rr]);
        __syncthreads();

        // O += P @ V  (64 x 64; each thread: 4 rows x 4 cols over d)
#pragma unroll
        for (int kk = 0; kk < 32; kk++) {
            float4 vf = *(const float4*)&Vs[kk][tx*4];
#pragma unroll
            for (int rr = 0; rr < 4; rr++) {
                float pv = KP[ty*4+rr][kk];
                o[rr][0] += pv*vf.x; o[rr][1] += pv*vf.y;
                o[rr][2] += pv*vf.z; o[rr][3] += pv*vf.w;
            }
        }
    }

    // finalize p@v part
#pragma unroll
    for (int rr = 0; rr < 4; rr++) {
        float inv = 1.0f / l_i[rr];
#pragma unroll
        for (int c = 0; c < 4; c++) o[rr][c] *= inv;
    }
    if (tx == 0) {
#pragma unroll
        for (int rr = 0; rr < 4; rr++) { mrow[ty*4+rr] = m_i[rr]; lrowv[ty*4+rr] = l_i[rr]; }
    }
    __syncthreads();

    // rel-V band: p(q, q-mm), mm = 0..31 (recompute; bucket identity:
    // out2 = table[0] + sum_mm p * (table[32-mm] - table[0]) since sum_k p = 1)
    float (*bandp)[32] = (float(*)[32])&KP[0][0];   // reuse (P dead)
#pragma unroll
    for (int i = 0; i < 8; i++) {
        int pidx = tid + 256*i;          // 2048 = 64 rows * 32 band offsets
        int row = pidx >> 5, mm = pidx & 31;
        int qg = qb*64 + row;
        int kg = qg - mm;
        float p = 0.f;
        if (kg >= 0) {
            const float* kvec = g_k + ((size_t)bh*SEQ + kg)*DHD;
            float dot = 0.f;
#pragma unroll
            for (int d = 0; d < 64; d += 4) {
                float4 kv = *(const float4*)(kvec + d);
                dot += Qs[row][d]*kv.x + Qs[row][d+1]*kv.y
                     + Qs[row][d+2]*kv.z + Qs[row][d+3]*kv.w;
            }
            float s = (dot + rel[row][32 - mm]) * 0.125f;
            p = __expf(s - mrow[row]) / lrowv[row];
        }
        bandp[row][mm] = p;
    }
    __syncthreads();

    float4 t0v = *(const float4*)&g_table[tx*4];
    float4 a2[4];
#pragma unroll
    for (int rr = 0; rr < 4; rr++) a2[rr] = t0v;
    for (int mm = 0; mm < 32; mm++) {
        float4 tv = *(const float4*)&g_table[(32 - mm)*64 + tx*4];
        float4 dv = make_float4(tv.x - t0v.x, tv.y - t0v.y, tv.z - t0v.z, tv.w - t0v.w);
#pragma unroll
        for (int rr = 0; rr < 4; rr++) {
            float pm = bandp[ty*4+rr][mm];
            a2[rr].x += pm*dv.x; a2[rr].y += pm*dv.y;
            a2[rr].z += pm*dv.z; a2[rr].w += pm*dv.w;
        }
    }
    int b = bh >> 3, h = bh & 7;
#pragma unroll
    for (int rr = 0; rr < 4; rr++) {
        int sg = qb*64 + ty*4 + rr;
        float4 ov = make_float4(o[rr][0] + a2[rr].x, o[rr][1] + a2[rr].y,
                                o[rr][2] + a2[rr].z, o[rr][3] + a2[rr].w);
        *(float4*)&g_attn[((size_t)b*SEQ + sg)*DMOD + h*64 + tx*4] = ov;
    }
}

// ---------------------------------------------------------------------------
// LayerNorm variant: unbiased std (ddof=1), divide by (std + eps)
__global__ __launch_bounds__(128) void ln_kernel(const float* __restrict__ lnw,
                                                 const float* __restrict__ lnb,
                                                 float* __restrict__ out)
{
    int rowid = blockIdx.x;
    const float* x = g_y + (size_t)rowid * DMOD;
    int tid = threadIdx.x;
    float4 xv = *(const float4*)(x + tid*4);
    float s  = xv.x + xv.y + xv.z + xv.w;
    float ss = xv.x*xv.x + xv.y*xv.y + xv.z*xv.z + xv.w*xv.w;
#pragma unroll
    for (int off = 16; off >= 1; off >>= 1) {
        s  += __shfl_xor_sync(0xffffffffu, s, off);
        ss += __shfl_xor_sync(0xffffffffu, ss, off);
    }
    __shared__ float rs[4], rss[4];
    int warp = tid >> 5;
    if ((tid & 31) == 0) { rs[warp] = s; rss[warp] = ss; }
    __syncthreads();
    float tS  = rs[0] + rs[1] + rs[2] + rs[3];
    float tSS = rss[0] + rss[1] + rss[2] + rss[3];
    float mean = tS * (1.0f/512.0f);
    float var = (tSS - 512.0f*mean*mean) * (1.0f/511.0f);
    var = fmaxf(var, 0.f);
    float inv = 1.0f / (sqrtf(var) + 1e-6f);
    float4 wv = *(const float4*)(lnw + tid*4);
    float4 bv = *(const float4*)(lnb + tid*4);
    float4 ov;
    ov.x = wv.x * (xv.x - mean) * inv + bv.x;
    ov.y = wv.y * (xv.y - mean) * inv + bv.y;
    ov.z = wv.z * (xv.z - mean) * inv + bv.z;
    ov.w = wv.w * (xv.w - mean) * inv + bv.w;
    *(float4*)(out + (size_t)rowid*DMOD + tid*4) = ov;
}

// ---------------------------------------------------------------------------
extern "C" void kernel_launch(void* const* d_in, const int* in_sizes, int n_in,
                              void* d_out, int out_size)
{
    const float* query = (const float*)d_in[0];
    const float* key_  = (const float*)d_in[1];
    const float* value = (const float*)d_in[2];
    const float* Wq = (const float*)d_in[3];
    const float* bq = (const float*)d_in[4];
    const float* Wk = (const float*)d_in[5];
    const float* bk = (const float*)d_in[6];
    const float* Wv = (const float*)d_in[7];
    const float* bv = (const float*)d_in[8];
    const float* Wo = (const float*)d_in[9];
    const float* bo = (const float*)d_in[10];
    const float* lnw = (const float*)d_in[11];
    const float* lnb = (const float*)d_in[12];
    float* out = (float*)d_out;
    (void)in_sizes; (void)n_in; (void)out_size;

    build_table_kernel<<<3, 1024>>>();
    gemm_qkv_kernel<<<dim3(8, 32, 3), 256>>>(query, key_, value,
                                             Wq, Wk, Wv, bq, bk, bv);
    attn_kernel<<<256, 256>>>();
    gemm_out_kernel<<<dim3(8, 32), 256>>>(Wo, bo, query);
    ln_kernel<<<NBS, 128>>>(lnw, lnb, out);
}